// round 15
// baseline (speedup 1.0000x reference)
#include <cuda_runtime.h>
#include <cuda_bf16.h>
#include <math.h>

#define BB   8
#define HH   128
#define WW   128
#define NN   (HH*WW)          // 16384
#define CC   64
#define NR   256
#define HID  256
#define EPSV 1e-5f
#define QSCALE 0.125f

__device__ float g_h  [BB*NN*CC];
__device__ float g_q  [BB*NN*CC];
__device__ float g_x2 [BB*NN*CC];
__device__ __nv_bfloat16 g_f [(size_t)BB*NN*HID];   // fc1 out (bf16 storage)
__device__ __nv_bfloat16 g_g [(size_t)BB*NN*HID];   // dw+gelu out (bf16 storage)
// fragment-packed operands
__device__ float g_kf [BB*16384];                   // K fragments
__device__ float g_vf [BB*16384];                   // (V @ proj_w) fragments
__device__ float g_srwfT[262144];                   // sr_w tf32 B-fragments (1 MB)

__device__ __forceinline__ float2 ffma2(const float2 a, const float2 b, const float2 c) {
    float2 d;
    asm("fma.rn.f32x2 %0, %1, %2, %3;"
        : "=l"(reinterpret_cast<unsigned long long&>(d))
        : "l"(reinterpret_cast<const unsigned long long&>(a)),
          "l"(reinterpret_cast<const unsigned long long&>(b)),
          "l"(reinterpret_cast<const unsigned long long&>(c)));
    return d;
}
__device__ __forceinline__ float2 dup2(float s) { return make_float2(s, s); }

__device__ __forceinline__ float tf32f(float f) {
    unsigned u;
    asm("cvt.rna.tf32.f32 %0, %1;" : "=r"(u) : "f"(f));
    return __uint_as_float(u);
}

// mma.sync m16n8k8 tf32
__device__ __forceinline__ void mma_tf32(float* c, const unsigned* a, float2 b) {
    unsigned b0 = __float_as_uint(b.x), b1 = __float_as_uint(b.y);
    asm volatile("mma.sync.aligned.m16n8k8.row.col.f32.tf32.tf32.f32 "
        "{%0,%1,%2,%3}, {%4,%5,%6,%7}, {%8,%9}, {%0,%1,%2,%3};"
        : "+f"(c[0]), "+f"(c[1]), "+f"(c[2]), "+f"(c[3])
        : "r"(a[0]), "r"(a[1]), "r"(a[2]), "r"(a[3]), "r"(b0), "r"(b1));
}

// =====================================================================
// K1: LN1 (fp32 h out) + q-proj via tf32 mma. grid 1024, block 256.
// =====================================================================
__global__ __launch_bounds__(256) void k1_ln_q(
    const float* __restrict__ x, const float* __restrict__ g1,
    const float* __restrict__ b1, const float* __restrict__ qw,
    const float* __restrict__ qb)
{
    extern __shared__ float sm1[];
    float* WF = sm1;            // [8 nt][8 kc][32 ln][2]
    float* As = sm1 + 4096;     // [128][68]
    int tid = threadIdx.x, warp = tid >> 5, lane = tid & 31;
    int gid = lane >> 2, tig = lane & 3;
    int rowbase = blockIdx.x * 128;

    for (int idx = tid; idx < 4096; idx += 256) {
        int nt = idx >> 9, kc = (idx >> 6) & 7, ln = (idx >> 1) & 31, j = idx & 1;
        int k = kc*8 + (ln & 3) + j*4;
        int col = nt*8 + (ln >> 2);
        WF[idx] = tf32f(qw[k*64 + col]);
    }

    float2 gg = ((const float2*)g1)[lane];
    float2 bbv = ((const float2*)b1)[lane];
    #pragma unroll
    for (int i = 0; i < 16; ++i) {
        int lr = warp*16 + i;
        int row = rowbase + lr;
        float2 v = ((const float2*)x)[row*32 + lane];
        float s = v.x + v.y, ss = v.x*v.x + v.y*v.y;
        #pragma unroll
        for (int o = 16; o; o >>= 1) {
            s  += __shfl_xor_sync(0xffffffffu, s,  o);
            ss += __shfl_xor_sync(0xffffffffu, ss, o);
        }
        float mean = s * (1.f/64.f);
        float rstd = rsqrtf(ss*(1.f/64.f) - mean*mean + EPSV);
        float2 hv;
        hv.x = (v.x - mean)*rstd*gg.x + bbv.x;
        hv.y = (v.y - mean)*rstd*gg.y + bbv.y;
        ((float2*)g_h)[row*32 + lane] = hv;
        float2 st = make_float2(tf32f(hv.x), tf32f(hv.y));
        *(float2*)&As[lr*68 + 2*lane] = st;
    }
    __syncthreads();

    float acc[8][4];
    #pragma unroll
    for (int nt = 0; nt < 8; ++nt)
        #pragma unroll
        for (int r = 0; r < 4; ++r) acc[nt][r] = 0.f;
    #pragma unroll
    for (int kc = 0; kc < 8; ++kc) {
        unsigned a[4];
        const float* ap = As + (warp*16 + gid)*68 + kc*8;
        a[0] = __float_as_uint(ap[tig]);
        a[1] = __float_as_uint(ap[8*68 + tig]);
        a[2] = __float_as_uint(ap[tig + 4]);
        a[3] = __float_as_uint(ap[8*68 + tig + 4]);
        #pragma unroll
        for (int nt = 0; nt < 8; ++nt) {
            float2 bv = *(const float2*)&WF[(nt*8 + kc)*64 + lane*2];
            mma_tf32(acc[nt], a, bv);
        }
    }

    #pragma unroll
    for (int nt = 0; nt < 8; ++nt) {
        int col = nt*8 + tig*2;
        float2 qbv = *(const float2*)&qb[col];
        int row = rowbase + warp*16 + gid;
        float2 o0 = make_float2((acc[nt][0] + qbv.x)*QSCALE, (acc[nt][1] + qbv.y)*QSCALE);
        float2 o1 = make_float2((acc[nt][2] + qbv.x)*QSCALE, (acc[nt][3] + qbv.y)*QSCALE);
        *(float2*)&g_q[(size_t)row*64 + col]     = o0;
        *(float2*)&g_q[(size_t)(row+8)*64 + col] = o1;
    }
}

// =====================================================================
// K2w: pack sr_w into tf32 m16n8k8 B-fragments. grid 1024, block 256.
// =====================================================================
__global__ __launch_bounds__(256) void k2w_pack(const float* __restrict__ srw)
{
    int t = blockIdx.x*256 + threadIdx.x;  // 0..262143
    int j  = t & 1;
    int ln = (t >> 1) & 31;
    int nt = (t >> 6) & 7;
    int kc = t >> 9;
    int k   = kc*8 + (ln & 3) + 4*j;
    int col = nt*8 + (ln >> 2);
    g_srwfT[t] = tf32f(srw[(size_t)k*64 + col]);
}

// =====================================================================
// K2: sr conv via tf32 mma (A from g_h) + LN + kv proj.
// Writes K and VP = V@proj_w DIRECTLY in mma B-fragment layout.
// grid 128, block 256. smem: xr [16][68] + vbuf [16][68] = 8704 B.
// =====================================================================
__global__ __launch_bounds__(256) void k2_sr_kv(
    const float* __restrict__ srb,
    const float* __restrict__ sng, const float* __restrict__ snb,
    const float* __restrict__ kvw, const float* __restrict__ kvb,
    const float* __restrict__ pw)
{
    extern __shared__ float sm2[];
    float* xr   = sm2;          // [16][68]
    float* vbuf = sm2 + 16*68;  // [16][68]
    int tid = threadIdx.x, warp = tid >> 5, lane = tid & 31;
    int gid = lane >> 2, tig = lane & 3;

    int basepos = blockIdx.x * 16;
    int b  = basepos >> 8;
    int keybase = basepos & 255;
    int oh = keybase >> 4;

    // ---- conv: m16 (positions) x n8 (out-ch tile = warp) x k4096 ----
    {
        float acc[4] = {0.f, 0.f, 0.f, 0.f};
        const float* hb = g_h + ((size_t)b*NN + (size_t)oh*8*WW)*64;
        const float2* bw = (const float2*)g_srwfT;
        int nt = warp;
        int pos0 = gid, pos1 = gid + 8;
        #pragma unroll 8
        for (int kc = 0; kc < 512; ++kc) {
            int i0 = kc >> 6;
            int p0 = (kc >> 3) & 7;
            int c0 = (kc & 7)*8 + tig;
            int off = (i0*WW + p0)*64 + c0;
            unsigned a[4];
            a[0] = __float_as_uint(tf32f(hb[off + pos0*512]));
            a[1] = __float_as_uint(tf32f(hb[off + pos1*512]));
            a[2] = __float_as_uint(tf32f(hb[off + pos0*512 + 4]));
            a[3] = __float_as_uint(tf32f(hb[off + pos1*512 + 4]));
            float2 bv = bw[(kc*8 + nt)*32 + lane];
            mma_tf32(acc, a, bv);
        }
        float2 sb2 = *(const float2*)&srb[nt*8 + 2*tig];
        int col = nt*8 + 2*tig;
        *(float2*)&xr[gid*68 + col]     = make_float2(acc[0] + sb2.x, acc[1] + sb2.y);
        *(float2*)&xr[(gid+8)*68 + col] = make_float2(acc[2] + sb2.x, acc[3] + sb2.y);
    }
    __syncthreads();

    // ---- LN over each of 16 rows (warp per 2 rows) ----
    {
        float2 sg  = ((const float2*)sng)[lane];
        float2 sbb = ((const float2*)snb)[lane];
        #pragma unroll
        for (int rr = 0; rr < 2; ++rr) {
            int r = warp*2 + rr;
            float2 v = ((float2*)xr)[r*34 + lane];
            float s = v.x + v.y, ss = v.x*v.x + v.y*v.y;
            #pragma unroll
            for (int o = 16; o; o >>= 1) {
                s  += __shfl_xor_sync(0xffffffffu, s,  o);
                ss += __shfl_xor_sync(0xffffffffu, ss, o);
            }
            float mean = s*(1.f/64.f);
            float rstd = rsqrtf(ss*(1.f/64.f) - mean*mean + EPSV);
            float2 nv;
            nv.x = (v.x-mean)*rstd*sg.x + sbb.x;
            nv.y = (v.y-mean)*rstd*sg.y + sbb.y;
            ((float2*)xr)[r*34 + lane] = nv;
        }
    }
    __syncthreads();

    // ---- kv proj: thread = kv channel (0..127) x row-half ----
    {
        int ch = tid & 127, rh = tid >> 7;
        float ak[8];
        float kb = kvb[ch];
        #pragma unroll
        for (int r = 0; r < 8; ++r) ak[r] = kb;
        #pragma unroll 4
        for (int j = 0; j < 64; ++j) {
            float w = kvw[j*128 + ch];
            #pragma unroll
            for (int r = 0; r < 8; ++r) ak[r] += xr[(rh*8 + r)*68 + j] * w;
        }
        if (ch < 64) {
            // K fragment stores: key = keybase + rh*8 + r, d = ch
            int d = ch;
            int kc = d >> 3, j = (d >> 2) & 1, lnlo = d & 3;
            #pragma unroll
            for (int r = 0; r < 8; ++r) {
                int key = keybase + rh*8 + r;
                int nt = key >> 3, ln = (key & 7)*4 + lnlo;
                g_kf[b*16384 + ((nt*8 + kc)*32 + ln)*2 + j] = ak[r];
            }
        } else {
            int d = ch - 64;
            #pragma unroll
            for (int r = 0; r < 8; ++r) vbuf[(rh*8 + r)*68 + d] = ak[r];
        }
    }
    __syncthreads();

    // ---- VP = v @ proj_w, stored in VF fragment layout ----
    {
        int col = tid & 63, kq = tid >> 6;   // kq = 0..3; keys kq, kq+4, kq+8, kq+12
        float vp[4] = {0.f, 0.f, 0.f, 0.f};
        #pragma unroll 8
        for (int d = 0; d < 64; ++d) {
            float w = pw[d*64 + col];
            #pragma unroll
            for (int kk = 0; kk < 4; ++kk)
                vp[kk] += vbuf[(kq + kk*4)*68 + d] * w;
        }
        int nt = col >> 3;
        #pragma unroll
        for (int kk = 0; kk < 4; ++kk) {
            int keyl = kq + kk*4;
            int key = keybase + keyl;
            int kc = key >> 3, j = (key >> 2) & 1;
            int ln = (col & 7)*4 + (key & 3);
            g_vf[b*16384 + ((nt*32 + kc)*32 + ln)*2 + j] = vp[kk];
        }
    }
}

// =====================================================================
// K3: attention via tf32 mma, proj folded into VP. 4 query-tiles/block.
// grid 512 (8 b x 64 groups), block 512 (16 warps).
// smem floats: KF 16384 | VF 16384 | S 64*260 | Qs 64*68 = 215040 B.
// =====================================================================
__global__ __launch_bounds__(512) void k3_attn(
    const float* __restrict__ x, const float* __restrict__ pb)
{
    extern __shared__ float sm3[];
    float* KF = sm3;                  // 16384
    float* VF = sm3 + 16384;          // 16384
    float* S  = sm3 + 32768;          // [64][260]
    float* Qs = sm3 + 32768 + 16640;  // [64][68]

    int tid = threadIdx.x, warp = tid >> 5, lane = tid & 31;
    int gid = lane >> 2, tig = lane & 3;
    int b = blockIdx.x >> 6, grp = blockIdx.x & 63;

    {
        const float4* kf4 = (const float4*)(g_kf + b*16384);
        const float4* vf4 = (const float4*)(g_vf + b*16384);
        float4* KF4 = (float4*)KF;
        float4* VF4 = (float4*)VF;
        #pragma unroll 4
        for (int i = tid; i < 4096; i += 512) { KF4[i] = kf4[i]; VF4[i] = vf4[i]; }
    }

    int wy = warp >> 2, wx = warp & 3;

    for (int it = 0; it < 4; ++it) {
        int q0 = (grp*4 + it) * 64;
        __syncthreads();
        {
            const float4* q4 = (const float4*)(g_q + ((size_t)b*NN + q0)*64);
            #pragma unroll
            for (int i = tid; i < 1024; i += 512) {
                int r = i >> 4, c = i & 15;
                *(float4*)&Qs[r*68 + c*4] = q4[i];
            }
        }
        __syncthreads();

        // ---- QK: warp tile m16 x n64 ----
        {
            float acc[8][4];
            #pragma unroll
            for (int nt = 0; nt < 8; ++nt)
                #pragma unroll
                for (int r = 0; r < 4; ++r) acc[nt][r] = 0.f;
            #pragma unroll
            for (int kc = 0; kc < 8; ++kc) {
                unsigned a[4];
                const float* ap = Qs + (wy*16 + gid)*68 + kc*8;
                a[0] = __float_as_uint(ap[tig]);
                a[1] = __float_as_uint(ap[8*68 + tig]);
                a[2] = __float_as_uint(ap[tig + 4]);
                a[3] = __float_as_uint(ap[8*68 + tig + 4]);
                #pragma unroll
                for (int nt = 0; nt < 8; ++nt) {
                    float2 bv = *(const float2*)&KF[((wx*8 + nt)*8 + kc)*64 + lane*2];
                    mma_tf32(acc[nt], a, bv);
                }
            }
            int r0 = wy*16 + gid;
            #pragma unroll
            for (int nt = 0; nt < 8; ++nt) {
                int cb = wx*64 + nt*8 + tig*2;
                *(float2*)&S[r0*260 + cb]     = make_float2(acc[nt][0], acc[nt][1]);
                *(float2*)&S[(r0+8)*260 + cb] = make_float2(acc[nt][2], acc[nt][3]);
            }
        }
        __syncthreads();

        // ---- softmax over 256 cols (warp per 4 rows) ----
        {
            float4* S4 = (float4*)S;       // row stride 65 float4
            #pragma unroll
            for (int i = 0; i < 4; ++i) {
                int r = warp*4 + i;
                float4 v0 = S4[r*65 + lane*2];
                float4 v1 = S4[r*65 + lane*2 + 1];
                float mx = fmaxf(fmaxf(fmaxf(v0.x, v0.y), fmaxf(v0.z, v0.w)),
                                 fmaxf(fmaxf(v1.x, v1.y), fmaxf(v1.z, v1.w)));
                #pragma unroll
                for (int o = 16; o; o >>= 1) mx = fmaxf(mx, __shfl_xor_sync(0xffffffffu, mx, o));
                v0.x = __expf(v0.x - mx); v0.y = __expf(v0.y - mx);
                v0.z = __expf(v0.z - mx); v0.w = __expf(v0.w - mx);
                v1.x = __expf(v1.x - mx); v1.y = __expf(v1.y - mx);
                v1.z = __expf(v1.z - mx); v1.w = __expf(v1.w - mx);
                float sum = v0.x + v0.y + v0.z + v0.w + v1.x + v1.y + v1.z + v1.w;
                #pragma unroll
                for (int o = 16; o; o >>= 1) sum += __shfl_xor_sync(0xffffffffu, sum, o);
                float inv = __frcp_rn(sum);
                v0.x *= inv; v0.y *= inv; v0.z *= inv; v0.w *= inv;
                v1.x *= inv; v1.y *= inv; v1.z *= inv; v1.w *= inv;
                S4[r*65 + lane*2]     = v0;
                S4[r*65 + lane*2 + 1] = v1;
            }
        }
        __syncthreads();

        // ---- P @ VP: warp tile m16 x n16, K=256; epilogue direct ----
        float accO[2][4];
        #pragma unroll
        for (int nt = 0; nt < 2; ++nt)
            #pragma unroll
            for (int r = 0; r < 4; ++r) accO[nt][r] = 0.f;
        #pragma unroll 4
        for (int kc = 0; kc < 32; ++kc) {
            unsigned a[4];
            const float* ap = S + (wy*16 + gid)*260 + kc*8;
            a[0] = __float_as_uint(ap[tig]);
            a[1] = __float_as_uint(ap[8*260 + tig]);
            a[2] = __float_as_uint(ap[tig + 4]);
            a[3] = __float_as_uint(ap[8*260 + tig + 4]);
            #pragma unroll
            for (int nt = 0; nt < 2; ++nt) {
                float2 bv = *(const float2*)&VF[((wx*2 + nt)*32 + kc)*64 + lane*2];
                mma_tf32(accO[nt], a, bv);
            }
        }

        // ---- epilogue: residual + bias ----
        #pragma unroll
        for (int nt = 0; nt < 2; ++nt) {
            int col = wx*16 + nt*8 + tig*2;
            float2 pbv = *(const float2*)&pb[col];
            size_t rowA = (size_t)b*NN + q0 + wy*16 + gid;
            size_t rowB = rowA + 8;
            float2 xa = *(const float2*)&x[rowA*64 + col];
            float2 xb = *(const float2*)&x[rowB*64 + col];
            float2 oa = make_float2(xa.x + accO[nt][0] + pbv.x, xa.y + accO[nt][1] + pbv.y);
            float2 ob = make_float2(xb.x + accO[nt][2] + pbv.x, xb.y + accO[nt][3] + pbv.y);
            *(float2*)&g_x2[rowA*64 + col] = oa;
            *(float2*)&g_x2[rowB*64 + col] = ob;
        }
    }
}

// =====================================================================
// K4: LN2 + fc1 via tf32 mma, bf16 output. grid 2048, block 256.
// =====================================================================
__global__ __launch_bounds__(256) void k4_ln_fc1(
    const float* __restrict__ g2, const float* __restrict__ b2,
    const float* __restrict__ w1, const float* __restrict__ fb1)
{
    extern __shared__ float sm4[];
    float* WF = sm4;            // [16 nt][8 kc][32 ln][2]
    float* As = sm4 + 8192;     // [128][68]
    int tid = threadIdx.x, warp = tid >> 5, lane = tid & 31;
    int gid = lane >> 2, tig = lane & 3;
    int cb = blockIdx.x & 1;
    int rowbase = (blockIdx.x >> 1) * 128;

    for (int idx = tid; idx < 8192; idx += 256) {
        int nt = idx >> 9, kc = (idx >> 6) & 7, ln = (idx >> 1) & 31, j = idx & 1;
        int k = kc*8 + (ln & 3) + j*4;
        int col = cb*128 + nt*8 + (ln >> 2);
        WF[idx] = tf32f(w1[k*256 + col]);
    }

    float2 gg = ((const float2*)g2)[lane];
    float2 bb = ((const float2*)b2)[lane];
    #pragma unroll
    for (int i = 0; i < 16; ++i) {
        int lr = warp*16 + i;
        int row = rowbase + lr;
        float2 v = ((const float2*)g_x2)[row*32 + lane];
        float s = v.x + v.y, ss = v.x*v.x + v.y*v.y;
        #pragma unroll
        for (int o = 16; o; o >>= 1) {
            s  += __shfl_xor_sync(0xffffffffu, s,  o);
            ss += __shfl_xor_sync(0xffffffffu, ss, o);
        }
        float mean = s*(1.f/64.f);
        float rstd = rsqrtf(ss*(1.f/64.f) - mean*mean + EPSV);
        float2 st;
        st.x = tf32f((v.x-mean)*rstd*gg.x + bb.x);
        st.y = tf32f((v.y-mean)*rstd*gg.y + bb.y);
        *(float2*)&As[lr*68 + 2*lane] = st;
    }
    __syncthreads();

    int wy = warp >> 1, wx = warp & 1;
    float acc[2][8][4];
    #pragma unroll
    for (int mt = 0; mt < 2; ++mt)
        #pragma unroll
        for (int nt = 0; nt < 8; ++nt)
            #pragma unroll
            for (int r = 0; r < 4; ++r) acc[mt][nt][r] = 0.f;

    #pragma unroll
    for (int kc = 0; kc < 8; ++kc) {
        unsigned a[2][4];
        #pragma unroll
        for (int mt = 0; mt < 2; ++mt) {
            const float* ap = As + (wy*32 + mt*16 + gid)*68 + kc*8;
            a[mt][0] = __float_as_uint(ap[tig]);
            a[mt][1] = __float_as_uint(ap[8*68 + tig]);
            a[mt][2] = __float_as_uint(ap[tig + 4]);
            a[mt][3] = __float_as_uint(ap[8*68 + tig + 4]);
        }
        #pragma unroll
        for (int nt = 0; nt < 8; ++nt) {
            float2 bv = *(const float2*)&WF[((wx*8 + nt)*8 + kc)*64 + lane*2];
            mma_tf32(acc[0][nt], a[0], bv);
            mma_tf32(acc[1][nt], a[1], bv);
        }
    }

    #pragma unroll
    for (int mt = 0; mt < 2; ++mt)
        #pragma unroll
        for (int nt = 0; nt < 8; ++nt) {
            int col = cb*128 + (wx*8 + nt)*8 + tig*2;
            float2 fbv = *(const float2*)&fb1[col];
            int row = rowbase + wy*32 + mt*16 + gid;
            float2 o0 = make_float2(acc[mt][nt][0] + fbv.x, acc[mt][nt][1] + fbv.y);
            float2 o1 = make_float2(acc[mt][nt][2] + fbv.x, acc[mt][nt][3] + fbv.y);
            *(__nv_bfloat162*)&g_f[(size_t)row*HID + col]     = __float22bfloat162_rn(o0);
            *(__nv_bfloat162*)&g_f[(size_t)(row+8)*HID + col] = __float22bfloat162_rn(o1);
        }
}

// =====================================================================
// K5: depthwise 3x3 SAME + GELU, bf16, smem-tiled rolling conv.
// block = (b, 8 h-rows, 32 channels). grid 1024, block 256. smem 81920 B.
// =====================================================================
__global__ __launch_bounds__(256) void k5_dw_gelu(const float* __restrict__ dww)
{
    extern __shared__ __nv_bfloat16 s5b[];   // [10][128][32] bf16
    int tid = threadIdx.x;
    int blk = blockIdx.x;
    int ct = blk & 7, ht = (blk >> 3) & 15, b = blk >> 7;
    int c0 = ct * 32, h0 = ht * 8;
    #pragma unroll
    for (int r = 0; r < 10; ++r) {
        int h = h0 - 1 + r;
        uint4* dst = (uint4*)(s5b + r*4096);       // 512 x uint4 (8 bf16 each)
        if ((unsigned)h < 128u) {
            const uint4* src = (const uint4*)(g_f + ((size_t)b*NN + (size_t)h*WW)*HID + c0);
            for (int i = tid; i < 512; i += 256) {
                int px = i >> 2, q = i & 3;
                dst[i] = src[px*32 + q];
            }
        } else {
            uint4 z = make_uint4(0u,0u,0u,0u);
            for (int i = tid; i < 512; i += 256) dst[i] = z;
        }
    }
    __syncthreads();

    int cp = tid & 15, wi = tid >> 4;
    float2 wt[9];
    #pragma unroll
    for (int t = 0; t < 9; ++t)
        wt[t] = *(const float2*)&dww[t*HID + c0 + 2*cp];

    const __nv_bfloat162* s5p = (const __nv_bfloat162*)s5b;  // pair units; row = 2048 pairs

    #pragma unroll
    for (int ro = 0; ro < 8; ++ro) {
        const __nv_bfloat162* r0p = s5p + ro*2048 + cp;
        const __nv_bfloat162* r1p = r0p + 2048;
        const __nv_bfloat162* r2p = r1p + 2048;
        int w = wi * 8;
        float2 L0, L1, L2, C0, C1, C2;
        if (w == 0) {
            L0 = L1 = L2 = make_float2(0.f, 0.f);
        } else {
            L0 = __bfloat1622float2(r0p[(w-1)*16]);
            L1 = __bfloat1622float2(r1p[(w-1)*16]);
            L2 = __bfloat1622float2(r2p[(w-1)*16]);
        }
        C0 = __bfloat1622float2(r0p[w*16]);
        C1 = __bfloat1622float2(r1p[w*16]);
        C2 = __bfloat1622float2(r2p[w*16]);
        #pragma unroll
        for (int k = 0; k < 8; ++k) {
            float2 N0, N1, N2;
            if (w + 1 < 128) {
                N0 = __bfloat1622float2(r0p[(w+1)*16]);
                N1 = __bfloat1622float2(r1p[(w+1)*16]);
                N2 = __bfloat1622float2(r2p[(w+1)*16]);
            } else {
                N0 = N1 = N2 = make_float2(0.f, 0.f);
            }
            float2 acc = make_float2(0.f, 0.f);
            acc = ffma2(L0, wt[0], acc); acc = ffma2(C0, wt[1], acc); acc = ffma2(N0, wt[2], acc);
            acc = ffma2(L1, wt[3], acc); acc = ffma2(C1, wt[4], acc); acc = ffma2(N1, wt[5], acc);
            acc = ffma2(L2, wt[6], acc); acc = ffma2(C2, wt[7], acc); acc = ffma2(N2, wt[8], acc);
            float2 o;
            o.x = acc.x * normcdff(acc.x);
            o.y = acc.y * normcdff(acc.y);
            *(__nv_bfloat162*)&g_g[((size_t)b*NN + (size_t)(h0+ro)*WW + w)*HID + c0 + 2*cp] =
                __float22bfloat162_rn(o);
            L0 = C0; L1 = C1; L2 = C2;
            C0 = N0; C1 = N1; C2 = N2;
            ++w;
        }
    }
}

// =====================================================================
// K6: fc2 (256->64) + residual via tf32 mma, bf16 A input. grid 1024, block 256.
// =====================================================================
__global__ __launch_bounds__(256) void k6_fc2(
    const float* __restrict__ w2, const float* __restrict__ b2,
    float* __restrict__ out)
{
    extern __shared__ float sm6[];
    float* WF = sm6;             // [8 nt][32 kc][32 ln][2] = 16384
    float* As = sm6 + 16384;     // [128][68]
    int tid = threadIdx.x, warp = tid >> 5, lane = tid & 31;
    int gid = lane >> 2, tig = lane & 3;
    int rowbase = blockIdx.x * 128;

    for (int idx = tid; idx < 16384; idx += 256) {
        int nt = idx >> 11, kc = (idx >> 6) & 31, ln = (idx >> 1) & 31, j = idx & 1;
        int k = kc*8 + (ln & 3) + j*4;
        int col = nt*8 + (ln >> 2);
        WF[idx] = tf32f(w2[k*64 + col]);
    }

    float acc[8][4];
    #pragma unroll
    for (int nt = 0; nt < 8; ++nt)
        #pragma unroll
        for (int r = 0; r < 4; ++r) acc[nt][r] = 0.f;

    for (int kblk = 0; kblk < 4; ++kblk) {
        __syncthreads();
        for (int i = tid; i < 1024; i += 256) {
            int row = i >> 3, q = i & 7;
            uint4 u = *(const uint4*)&g_g[(size_t)(rowbase+row)*HID + kblk*64 + q*8];
            float2 f0 = __bfloat1622float2(*(__nv_bfloat162*)&u.x);
            float2 f1 = __bfloat1622float2(*(__nv_bfloat162*)&u.y);
            float2 f2 = __bfloat1622float2(*(__nv_bfloat162*)&u.z);
            float2 f3 = __bfloat1622float2(*(__nv_bfloat162*)&u.w);
            float* dp = &As[row*68 + q*8];
            dp[0] = f0.x; dp[1] = f0.y; dp[2] = f1.x; dp[3] = f1.y;
            dp[4] = f2.x; dp[5] = f2.y; dp[6] = f3.x; dp[7] = f3.y;
        }
        __syncthreads();
        #pragma unroll
        for (int kc = 0; kc < 8; ++kc) {
            unsigned a[4];
            const float* ap = As + (warp*16 + gid)*68 + kc*8;
            a[0] = __float_as_uint(ap[tig]);
            a[1] = __float_as_uint(ap[8*68 + tig]);
            a[2] = __float_as_uint(ap[tig + 4]);
            a[3] = __float_as_uint(ap[8*68 + tig + 4]);
            #pragma unroll
            for (int nt = 0; nt < 8; ++nt) {
                float2 bv = *(const float2*)&WF[(nt*32 + kblk*8 + kc)*64 + lane*2];
                mma_tf32(acc[nt], a, bv);
            }
        }
    }

    #pragma unroll
    for (int nt = 0; nt < 8; ++nt) {
        int col = nt*8 + tig*2;
        float2 bbv = *(const float2*)&b2[col];
        int row = rowbase + warp*16 + gid;
        float2 r0 = *(const float2*)&g_x2[(size_t)row*CC + col];
        float2 r1 = *(const float2*)&g_x2[(size_t)(row+8)*CC + col];
        float2 o0 = make_float2(r0.x + acc[nt][0] + bbv.x, r0.y + acc[nt][1] + bbv.y);
        float2 o1 = make_float2(r1.x + acc[nt][2] + bbv.x, r1.y + acc[nt][3] + bbv.y);
        *(float2*)&out[(size_t)row*CC + col]     = o0;
        *(float2*)&out[(size_t)(row+8)*CC + col] = o1;
    }
}

// =====================================================================
extern "C" void kernel_launch(void* const* d_in, const int* in_sizes, int n_in,
                              void* d_out, int out_size)
{
    const float* x     = (const float*)d_in[0];
    const float* ln1_g = (const float*)d_in[3];
    const float* ln1_b = (const float*)d_in[4];
    const float* q_w   = (const float*)d_in[5];
    const float* q_b   = (const float*)d_in[6];
    const float* kv_w  = (const float*)d_in[7];
    const float* kv_b  = (const float*)d_in[8];
    const float* pr_w  = (const float*)d_in[9];
    const float* pr_b  = (const float*)d_in[10];
    const float* sr_w  = (const float*)d_in[11];
    const float* sr_b  = (const float*)d_in[12];
    const float* srn_g = (const float*)d_in[13];
    const float* srn_b = (const float*)d_in[14];
    const float* ln2_g = (const float*)d_in[15];
    const float* ln2_b = (const float*)d_in[16];
    const float* fc1_w = (const float*)d_in[17];
    const float* fc1_b = (const float*)d_in[18];
    const float* dw_w  = (const float*)d_in[19];
    const float* fc2_w = (const float*)d_in[20];
    const float* fc2_b = (const float*)d_in[21];
    float* out = (float*)d_out;

    const int K1_SMEM = (4096 + 128*68) * 4;                    // 51200
    const int K2_SMEM = 2*16*68*4;                              // 8704
    const int K3_SMEM = (16384 + 16384 + 64*260 + 64*68) * 4;   // 215040
    const int K4_SMEM = (8192 + 128*68) * 4;                    // 67584
    const int K5_SMEM = 10*128*32*2;                            // 81920
    const int K6_SMEM = (16384 + 128*68) * 4;                   // 100352

    cudaFuncSetAttribute(k1_ln_q,   cudaFuncAttributeMaxDynamicSharedMemorySize, K1_SMEM);
    cudaFuncSetAttribute(k3_attn,   cudaFuncAttributeMaxDynamicSharedMemorySize, K3_SMEM);
    cudaFuncSetAttribute(k4_ln_fc1, cudaFuncAttributeMaxDynamicSharedMemorySize, K4_SMEM);
    cudaFuncSetAttribute(k5_dw_gelu,cudaFuncAttributeMaxDynamicSharedMemorySize, K5_SMEM);
    cudaFuncSetAttribute(k6_fc2,    cudaFuncAttributeMaxDynamicSharedMemorySize, K6_SMEM);

    k1_ln_q  <<<1024, 256, K1_SMEM>>>(x, ln1_g, ln1_b, q_w, q_b);
    k2w_pack <<<1024, 256>>>(sr_w);
    k2_sr_kv <<<128, 256, K2_SMEM>>>(sr_b, srn_g, srn_b, kv_w, kv_b, pr_w);
    k3_attn  <<<512, 512, K3_SMEM>>>(x, pr_b);
    k4_ln_fc1<<<2048, 256, K4_SMEM>>>(ln2_g, ln2_b, fc1_w, fc1_b);
    k5_dw_gelu<<<1024, 256, K5_SMEM>>>(dw_w);
    k6_fc2   <<<1024, 256, K6_SMEM>>>(fc2_w, fc2_b, out);
}

// round 16
// speedup vs baseline: 1.0378x; 1.0378x over previous
#include <cuda_runtime.h>
#include <cuda_bf16.h>
#include <math.h>

#define BB   8
#define HH   128
#define WW   128
#define NN   (HH*WW)          // 16384
#define CC   64
#define NR   256
#define HID  256
#define EPSV 1e-5f
#define QSCALE 0.125f

__device__ float g_h  [BB*NN*CC];
__device__ float g_q  [BB*NN*CC];
__device__ float g_x2 [BB*NN*CC];
__device__ __nv_bfloat16 g_f [(size_t)BB*NN*HID];   // fc1 out (bf16 storage)
__device__ __nv_bfloat16 g_g [(size_t)BB*NN*HID];   // dw+gelu out (bf16 storage)
// fragment-packed operands
__device__ float g_kf [BB*16384];                   // K fragments
__device__ float g_vf [BB*16384];                   // (V @ proj_w) fragments
__device__ float g_srwfT[262144];                   // sr_w tf32 B-fragments (1 MB)

__device__ __forceinline__ float2 ffma2(const float2 a, const float2 b, const float2 c) {
    float2 d;
    asm("fma.rn.f32x2 %0, %1, %2, %3;"
        : "=l"(reinterpret_cast<unsigned long long&>(d))
        : "l"(reinterpret_cast<const unsigned long long&>(a)),
          "l"(reinterpret_cast<const unsigned long long&>(b)),
          "l"(reinterpret_cast<const unsigned long long&>(c)));
    return d;
}
__device__ __forceinline__ float2 dup2(float s) { return make_float2(s, s); }

__device__ __forceinline__ float tf32f(float f) {
    unsigned u;
    asm("cvt.rna.tf32.f32 %0, %1;" : "=r"(u) : "f"(f));
    return __uint_as_float(u);
}

// mma.sync m16n8k8 tf32
__device__ __forceinline__ void mma_tf32(float* c, const unsigned* a, float2 b) {
    unsigned b0 = __float_as_uint(b.x), b1 = __float_as_uint(b.y);
    asm volatile("mma.sync.aligned.m16n8k8.row.col.f32.tf32.tf32.f32 "
        "{%0,%1,%2,%3}, {%4,%5,%6,%7}, {%8,%9}, {%0,%1,%2,%3};"
        : "+f"(c[0]), "+f"(c[1]), "+f"(c[2]), "+f"(c[3])
        : "r"(a[0]), "r"(a[1]), "r"(a[2]), "r"(a[3]), "r"(b0), "r"(b1));
}

// mma.sync m16n8k16 bf16
__device__ __forceinline__ void mma_bf16(float* c, const unsigned* a, const unsigned* b) {
    asm volatile("mma.sync.aligned.m16n8k16.row.col.f32.bf16.bf16.f32 "
        "{%0,%1,%2,%3}, {%4,%5,%6,%7}, {%8,%9}, {%0,%1,%2,%3};"
        : "+f"(c[0]), "+f"(c[1]), "+f"(c[2]), "+f"(c[3])
        : "r"(a[0]), "r"(a[1]), "r"(a[2]), "r"(a[3]), "r"(b[0]), "r"(b[1]));
}

// =====================================================================
// K1: LN1 (fp32 h out) + q-proj via tf32 mma. grid 1024, block 256.
// =====================================================================
__global__ __launch_bounds__(256) void k1_ln_q(
    const float* __restrict__ x, const float* __restrict__ g1,
    const float* __restrict__ b1, const float* __restrict__ qw,
    const float* __restrict__ qb)
{
    extern __shared__ float sm1[];
    float* WF = sm1;            // [8 nt][8 kc][32 ln][2]
    float* As = sm1 + 4096;     // [128][68]
    int tid = threadIdx.x, warp = tid >> 5, lane = tid & 31;
    int gid = lane >> 2, tig = lane & 3;
    int rowbase = blockIdx.x * 128;

    for (int idx = tid; idx < 4096; idx += 256) {
        int nt = idx >> 9, kc = (idx >> 6) & 7, ln = (idx >> 1) & 31, j = idx & 1;
        int k = kc*8 + (ln & 3) + j*4;
        int col = nt*8 + (ln >> 2);
        WF[idx] = tf32f(qw[k*64 + col]);
    }

    float2 gg = ((const float2*)g1)[lane];
    float2 bbv = ((const float2*)b1)[lane];
    #pragma unroll
    for (int i = 0; i < 16; ++i) {
        int lr = warp*16 + i;
        int row = rowbase + lr;
        float2 v = ((const float2*)x)[row*32 + lane];
        float s = v.x + v.y, ss = v.x*v.x + v.y*v.y;
        #pragma unroll
        for (int o = 16; o; o >>= 1) {
            s  += __shfl_xor_sync(0xffffffffu, s,  o);
            ss += __shfl_xor_sync(0xffffffffu, ss, o);
        }
        float mean = s * (1.f/64.f);
        float rstd = rsqrtf(ss*(1.f/64.f) - mean*mean + EPSV);
        float2 hv;
        hv.x = (v.x - mean)*rstd*gg.x + bbv.x;
        hv.y = (v.y - mean)*rstd*gg.y + bbv.y;
        ((float2*)g_h)[row*32 + lane] = hv;
        float2 st = make_float2(tf32f(hv.x), tf32f(hv.y));
        *(float2*)&As[lr*68 + 2*lane] = st;
    }
    __syncthreads();

    float acc[8][4];
    #pragma unroll
    for (int nt = 0; nt < 8; ++nt)
        #pragma unroll
        for (int r = 0; r < 4; ++r) acc[nt][r] = 0.f;
    #pragma unroll
    for (int kc = 0; kc < 8; ++kc) {
        unsigned a[4];
        const float* ap = As + (warp*16 + gid)*68 + kc*8;
        a[0] = __float_as_uint(ap[tig]);
        a[1] = __float_as_uint(ap[8*68 + tig]);
        a[2] = __float_as_uint(ap[tig + 4]);
        a[3] = __float_as_uint(ap[8*68 + tig + 4]);
        #pragma unroll
        for (int nt = 0; nt < 8; ++nt) {
            float2 bv = *(const float2*)&WF[(nt*8 + kc)*64 + lane*2];
            mma_tf32(acc[nt], a, bv);
        }
    }

    #pragma unroll
    for (int nt = 0; nt < 8; ++nt) {
        int col = nt*8 + tig*2;
        float2 qbv = *(const float2*)&qb[col];
        int row = rowbase + warp*16 + gid;
        float2 o0 = make_float2((acc[nt][0] + qbv.x)*QSCALE, (acc[nt][1] + qbv.y)*QSCALE);
        float2 o1 = make_float2((acc[nt][2] + qbv.x)*QSCALE, (acc[nt][3] + qbv.y)*QSCALE);
        *(float2*)&g_q[(size_t)row*64 + col]     = o0;
        *(float2*)&g_q[(size_t)(row+8)*64 + col] = o1;
    }
}

// =====================================================================
// K2w: pack sr_w into tf32 m16n8k8 B-fragments. grid 1024, block 256.
// =====================================================================
__global__ __launch_bounds__(256) void k2w_pack(const float* __restrict__ srw)
{
    int t = blockIdx.x*256 + threadIdx.x;  // 0..262143
    int j  = t & 1;
    int ln = (t >> 1) & 31;
    int nt = (t >> 6) & 7;
    int kc = t >> 9;
    int k   = kc*8 + (ln & 3) + 4*j;
    int col = nt*8 + (ln >> 2);
    g_srwfT[t] = tf32f(srw[(size_t)k*64 + col]);
}

// =====================================================================
// K2: sr conv via tf32 mma (A from g_h) + LN + kv proj.
// Writes K and VP = V@proj_w DIRECTLY in mma B-fragment layout.
// grid 128, block 256. smem: xr [16][68] + vbuf [16][68] = 8704 B.
// =====================================================================
__global__ __launch_bounds__(256) void k2_sr_kv(
    const float* __restrict__ srb,
    const float* __restrict__ sng, const float* __restrict__ snb,
    const float* __restrict__ kvw, const float* __restrict__ kvb,
    const float* __restrict__ pw)
{
    extern __shared__ float sm2[];
    float* xr   = sm2;          // [16][68]
    float* vbuf = sm2 + 16*68;  // [16][68]
    int tid = threadIdx.x, warp = tid >> 5, lane = tid & 31;
    int gid = lane >> 2, tig = lane & 3;

    int basepos = blockIdx.x * 16;
    int b  = basepos >> 8;
    int keybase = basepos & 255;
    int oh = keybase >> 4;

    // ---- conv: m16 (positions) x n8 (out-ch tile = warp) x k4096 ----
    {
        float acc[4] = {0.f, 0.f, 0.f, 0.f};
        const float* hb = g_h + ((size_t)b*NN + (size_t)oh*8*WW)*64;
        const float2* bw = (const float2*)g_srwfT;
        int nt = warp;
        int pos0 = gid, pos1 = gid + 8;
        #pragma unroll 8
        for (int kc = 0; kc < 512; ++kc) {
            int i0 = kc >> 6;
            int p0 = (kc >> 3) & 7;
            int c0 = (kc & 7)*8 + tig;
            int off = (i0*WW + p0)*64 + c0;
            unsigned a[4];
            a[0] = __float_as_uint(tf32f(hb[off + pos0*512]));
            a[1] = __float_as_uint(tf32f(hb[off + pos1*512]));
            a[2] = __float_as_uint(tf32f(hb[off + pos0*512 + 4]));
            a[3] = __float_as_uint(tf32f(hb[off + pos1*512 + 4]));
            float2 bv = bw[(kc*8 + nt)*32 + lane];
            mma_tf32(acc, a, bv);
        }
        float2 sb2 = *(const float2*)&srb[nt*8 + 2*tig];
        int col = nt*8 + 2*tig;
        *(float2*)&xr[gid*68 + col]     = make_float2(acc[0] + sb2.x, acc[1] + sb2.y);
        *(float2*)&xr[(gid+8)*68 + col] = make_float2(acc[2] + sb2.x, acc[3] + sb2.y);
    }
    __syncthreads();

    // ---- LN over each of 16 rows (warp per 2 rows) ----
    {
        float2 sg  = ((const float2*)sng)[lane];
        float2 sbb = ((const float2*)snb)[lane];
        #pragma unroll
        for (int rr = 0; rr < 2; ++rr) {
            int r = warp*2 + rr;
            float2 v = ((float2*)xr)[r*34 + lane];
            float s = v.x + v.y, ss = v.x*v.x + v.y*v.y;
            #pragma unroll
            for (int o = 16; o; o >>= 1) {
                s  += __shfl_xor_sync(0xffffffffu, s,  o);
                ss += __shfl_xor_sync(0xffffffffu, ss, o);
            }
            float mean = s*(1.f/64.f);
            float rstd = rsqrtf(ss*(1.f/64.f) - mean*mean + EPSV);
            float2 nv;
            nv.x = (v.x-mean)*rstd*sg.x + sbb.x;
            nv.y = (v.y-mean)*rstd*sg.y + sbb.y;
            ((float2*)xr)[r*34 + lane] = nv;
        }
    }
    __syncthreads();

    // ---- kv proj: thread = kv channel (0..127) x row-half ----
    {
        int ch = tid & 127, rh = tid >> 7;
        float ak[8];
        float kb = kvb[ch];
        #pragma unroll
        for (int r = 0; r < 8; ++r) ak[r] = kb;
        #pragma unroll 4
        for (int j = 0; j < 64; ++j) {
            float w = kvw[j*128 + ch];
            #pragma unroll
            for (int r = 0; r < 8; ++r) ak[r] += xr[(rh*8 + r)*68 + j] * w;
        }
        if (ch < 64) {
            int d = ch;
            int kc = d >> 3, j = (d >> 2) & 1, lnlo = d & 3;
            #pragma unroll
            for (int r = 0; r < 8; ++r) {
                int key = keybase + rh*8 + r;
                int nt = key >> 3, ln = (key & 7)*4 + lnlo;
                g_kf[b*16384 + ((nt*8 + kc)*32 + ln)*2 + j] = ak[r];
            }
        } else {
            int d = ch - 64;
            #pragma unroll
            for (int r = 0; r < 8; ++r) vbuf[(rh*8 + r)*68 + d] = ak[r];
        }
    }
    __syncthreads();

    // ---- VP = v @ proj_w, stored in VF fragment layout ----
    {
        int col = tid & 63, kq = tid >> 6;   // kq = 0..3; keys kq, kq+4, kq+8, kq+12
        float vp[4] = {0.f, 0.f, 0.f, 0.f};
        #pragma unroll 8
        for (int d = 0; d < 64; ++d) {
            float w = pw[d*64 + col];
            #pragma unroll
            for (int kk = 0; kk < 4; ++kk)
                vp[kk] += vbuf[(kq + kk*4)*68 + d] * w;
        }
        int nt = col >> 3;
        #pragma unroll
        for (int kk = 0; kk < 4; ++kk) {
            int keyl = kq + kk*4;
            int key = keybase + keyl;
            int kc = key >> 3, j = (key >> 2) & 1;
            int ln = (col & 7)*4 + (key & 3);
            g_vf[b*16384 + ((nt*32 + kc)*32 + ln)*2 + j] = vp[kk];
        }
    }
}

// =====================================================================
// K3: attention via tf32 mma, proj folded into VP. 4 query-tiles/block.
// grid 512, block 512 (16 warps). Q prefetched in registers (pipelined).
// smem floats: KF 16384 | VF 16384 | S 64*260 | Qs 64*68 = 215040 B.
// =====================================================================
__global__ __launch_bounds__(512) void k3_attn(
    const float* __restrict__ x, const float* __restrict__ pb)
{
    extern __shared__ float sm3[];
    float* KF = sm3;                  // 16384
    float* VF = sm3 + 16384;          // 16384
    float* S  = sm3 + 32768;          // [64][260]
    float* Qs = sm3 + 32768 + 16640;  // [64][68]

    int tid = threadIdx.x, warp = tid >> 5, lane = tid & 31;
    int gid = lane >> 2, tig = lane & 3;
    int b = blockIdx.x >> 6, grp = blockIdx.x & 63;

    {
        const float4* kf4 = (const float4*)(g_kf + b*16384);
        const float4* vf4 = (const float4*)(g_vf + b*16384);
        float4* KF4 = (float4*)KF;
        float4* VF4 = (float4*)VF;
        #pragma unroll 4
        for (int i = tid; i < 4096; i += 512) { KF4[i] = kf4[i]; VF4[i] = vf4[i]; }
    }

    int wy = warp >> 2, wx = warp & 3;

    // prefetch Q tile 0 into registers
    float4 qr0, qr1;
    {
        const float4* q4 = (const float4*)(g_q + ((size_t)b*NN + (size_t)grp*256)*64);
        qr0 = q4[tid]; qr1 = q4[tid + 512];
    }
    __syncthreads();   // KF/VF staged
    {
        ((float4*)Qs)[(tid >> 4)*17 + (tid & 15)] = qr0;
        int i1 = tid + 512;
        ((float4*)Qs)[(i1 >> 4)*17 + (i1 & 15)] = qr1;
    }
    __syncthreads();   // Qs(Q0) ready

    for (int it = 0; it < 4; ++it) {
        int q0 = (grp*4 + it) * 64;

        // ---- QK: warp tile m16 x n64 ----
        {
            float acc[8][4];
            #pragma unroll
            for (int nt = 0; nt < 8; ++nt)
                #pragma unroll
                for (int r = 0; r < 4; ++r) acc[nt][r] = 0.f;
            #pragma unroll
            for (int kc = 0; kc < 8; ++kc) {
                unsigned a[4];
                const float* ap = Qs + (wy*16 + gid)*68 + kc*8;
                a[0] = __float_as_uint(ap[tig]);
                a[1] = __float_as_uint(ap[8*68 + tig]);
                a[2] = __float_as_uint(ap[tig + 4]);
                a[3] = __float_as_uint(ap[8*68 + tig + 4]);
                #pragma unroll
                for (int nt = 0; nt < 8; ++nt) {
                    float2 bv = *(const float2*)&KF[((wx*8 + nt)*8 + kc)*64 + lane*2];
                    mma_tf32(acc[nt], a, bv);
                }
            }
            int r0 = wy*16 + gid;
            #pragma unroll
            for (int nt = 0; nt < 8; ++nt) {
                int cb = wx*64 + nt*8 + tig*2;
                *(float2*)&S[r0*260 + cb]     = make_float2(acc[nt][0], acc[nt][1]);
                *(float2*)&S[(r0+8)*260 + cb] = make_float2(acc[nt][2], acc[nt][3]);
            }
        }
        __syncthreads();

        // ---- softmax (warp per 4 rows) + prefetch next Q ----
        {
            float4* S4 = (float4*)S;       // row stride 65 float4
            #pragma unroll
            for (int i = 0; i < 4; ++i) {
                int r = warp*4 + i;
                float4 v0 = S4[r*65 + lane*2];
                float4 v1 = S4[r*65 + lane*2 + 1];
                float mx = fmaxf(fmaxf(fmaxf(v0.x, v0.y), fmaxf(v0.z, v0.w)),
                                 fmaxf(fmaxf(v1.x, v1.y), fmaxf(v1.z, v1.w)));
                #pragma unroll
                for (int o = 16; o; o >>= 1) mx = fmaxf(mx, __shfl_xor_sync(0xffffffffu, mx, o));
                v0.x = __expf(v0.x - mx); v0.y = __expf(v0.y - mx);
                v0.z = __expf(v0.z - mx); v0.w = __expf(v0.w - mx);
                v1.x = __expf(v1.x - mx); v1.y = __expf(v1.y - mx);
                v1.z = __expf(v1.z - mx); v1.w = __expf(v1.w - mx);
                float sum = v0.x + v0.y + v0.z + v0.w + v1.x + v1.y + v1.z + v1.w;
                #pragma unroll
                for (int o = 16; o; o >>= 1) sum += __shfl_xor_sync(0xffffffffu, sum, o);
                float inv = __frcp_rn(sum);
                v0.x *= inv; v0.y *= inv; v0.z *= inv; v0.w *= inv;
                v1.x *= inv; v1.y *= inv; v1.z *= inv; v1.w *= inv;
                S4[r*65 + lane*2]     = v0;
                S4[r*65 + lane*2 + 1] = v1;
            }
            if (it < 3) {
                const float4* q4 = (const float4*)(g_q + ((size_t)b*NN + q0 + 64)*64);
                qr0 = q4[tid]; qr1 = q4[tid + 512];
            }
        }
        __syncthreads();

        // ---- P @ VP: warp tile m16 x n16, K=256 ----
        float accO[2][4];
        #pragma unroll
        for (int nt = 0; nt < 2; ++nt)
            #pragma unroll
            for (int r = 0; r < 4; ++r) accO[nt][r] = 0.f;
        #pragma unroll 4
        for (int kc = 0; kc < 32; ++kc) {
            unsigned a[4];
            const float* ap = S + (wy*16 + gid)*260 + kc*8;
            a[0] = __float_as_uint(ap[tig]);
            a[1] = __float_as_uint(ap[8*260 + tig]);
            a[2] = __float_as_uint(ap[tig + 4]);
            a[3] = __float_as_uint(ap[8*260 + tig + 4]);
            #pragma unroll
            for (int nt = 0; nt < 2; ++nt) {
                float2 bv = *(const float2*)&VF[((wx*2 + nt)*32 + kc)*64 + lane*2];
                mma_tf32(accO[nt], a, bv);
            }
        }

        // ---- epilogue + commit next Q to smem ----
        #pragma unroll
        for (int nt = 0; nt < 2; ++nt) {
            int col = wx*16 + nt*8 + tig*2;
            float2 pbv = *(const float2*)&pb[col];
            size_t rowA = (size_t)b*NN + q0 + wy*16 + gid;
            size_t rowB = rowA + 8;
            float2 xa = *(const float2*)&x[rowA*64 + col];
            float2 xb = *(const float2*)&x[rowB*64 + col];
            float2 oa = make_float2(xa.x + accO[nt][0] + pbv.x, xa.y + accO[nt][1] + pbv.y);
            float2 ob = make_float2(xb.x + accO[nt][2] + pbv.x, xb.y + accO[nt][3] + pbv.y);
            *(float2*)&g_x2[rowA*64 + col] = oa;
            *(float2*)&g_x2[rowB*64 + col] = ob;
        }
        if (it < 3) {
            ((float4*)Qs)[(tid >> 4)*17 + (tid & 15)] = qr0;
            int i1 = tid + 512;
            ((float4*)Qs)[(i1 >> 4)*17 + (i1 & 15)] = qr1;
        }
        __syncthreads();   // S + Qs safe for next tile
    }
}

// =====================================================================
// K4: LN2 + fc1 via bf16 m16n8k16 mma, bf16 output. grid 2048, block 256.
// smem: WF 4096 words (16 KB) + As [128][72] bf16 (18 KB) = 34816 B.
// =====================================================================
__global__ __launch_bounds__(256) void k4_ln_fc1(
    const float* __restrict__ g2, const float* __restrict__ b2,
    const float* __restrict__ w1, const float* __restrict__ fb1)
{
    extern __shared__ char sm4raw[];
    unsigned* WFw = (unsigned*)sm4raw;                   // [16 nt][4 kc][32 ln][2 j]
    __nv_bfloat16* As = (__nv_bfloat16*)(sm4raw + 16384); // [128][72]
    int tid = threadIdx.x, warp = tid >> 5, lane = tid & 31;
    int gid = lane >> 2, tig = lane & 3;
    int cb = blockIdx.x & 1;
    int rowbase = (blockIdx.x >> 1) * 128;

    for (int idx = tid; idx < 4096; idx += 256) {
        int j = idx & 1, ln = (idx >> 1) & 31, kc = (idx >> 6) & 3, nt = idx >> 8;
        int g_ = ln >> 2, t_ = ln & 3;
        int k0 = kc*16 + 2*t_ + j*8;
        int col = cb*128 + nt*8 + g_;
        __nv_bfloat162 p = __float22bfloat162_rn(
            make_float2(w1[k0*256 + col], w1[(k0+1)*256 + col]));
        WFw[idx] = *(unsigned*)&p;
    }

    float2 gg = ((const float2*)g2)[lane];
    float2 bb = ((const float2*)b2)[lane];
    #pragma unroll
    for (int i = 0; i < 16; ++i) {
        int lr = warp*16 + i;
        int row = rowbase + lr;
        float2 v = ((const float2*)g_x2)[row*32 + lane];
        float s = v.x + v.y, ss = v.x*v.x + v.y*v.y;
        #pragma unroll
        for (int o = 16; o; o >>= 1) {
            s  += __shfl_xor_sync(0xffffffffu, s,  o);
            ss += __shfl_xor_sync(0xffffffffu, ss, o);
        }
        float mean = s*(1.f/64.f);
        float rstd = rsqrtf(ss*(1.f/64.f) - mean*mean + EPSV);
        float2 st;
        st.x = (v.x-mean)*rstd*gg.x + bb.x;
        st.y = (v.y-mean)*rstd*gg.y + bb.y;
        *(__nv_bfloat162*)&As[lr*72 + 2*lane] = __float22bfloat162_rn(st);
    }
    __syncthreads();

    const unsigned* Asw = (const unsigned*)As;   // word stride 36 per row
    const uint2* WFu2 = (const uint2*)WFw;
    int wy = warp >> 1, wx = warp & 1;
    float acc[2][8][4];
    #pragma unroll
    for (int mt = 0; mt < 2; ++mt)
        #pragma unroll
        for (int nt = 0; nt < 8; ++nt)
            #pragma unroll
            for (int r = 0; r < 4; ++r) acc[mt][nt][r] = 0.f;

    #pragma unroll
    for (int kc = 0; kc < 4; ++kc) {
        unsigned a[2][4];
        #pragma unroll
        for (int mt = 0; mt < 2; ++mt) {
            int base = (wy*32 + mt*16 + gid)*36 + kc*8;
            a[mt][0] = Asw[base + tig];
            a[mt][1] = Asw[base + 8*36 + tig];
            a[mt][2] = Asw[base + tig + 4];
            a[mt][3] = Asw[base + 8*36 + tig + 4];
        }
        #pragma unroll
        for (int nt = 0; nt < 8; ++nt) {
            uint2 bv = WFu2[((wx*8 + nt)*4 + kc)*32 + lane];
            mma_bf16(acc[0][nt], a[0], (const unsigned*)&bv);
            mma_bf16(acc[1][nt], a[1], (const unsigned*)&bv);
        }
    }

    #pragma unroll
    for (int mt = 0; mt < 2; ++mt)
        #pragma unroll
        for (int nt = 0; nt < 8; ++nt) {
            int col = cb*128 + (wx*8 + nt)*8 + tig*2;
            float2 fbv = *(const float2*)&fb1[col];
            int row = rowbase + wy*32 + mt*16 + gid;
            float2 o0 = make_float2(acc[mt][nt][0] + fbv.x, acc[mt][nt][1] + fbv.y);
            float2 o1 = make_float2(acc[mt][nt][2] + fbv.x, acc[mt][nt][3] + fbv.y);
            *(__nv_bfloat162*)&g_f[(size_t)row*HID + col]     = __float22bfloat162_rn(o0);
            *(__nv_bfloat162*)&g_f[(size_t)(row+8)*HID + col] = __float22bfloat162_rn(o1);
        }
}

// =====================================================================
// K5: depthwise 3x3 SAME + GELU, bf16, smem-tiled rolling conv.
// block = (b, 8 h-rows, 32 channels). grid 1024, block 256. smem 81920 B.
// =====================================================================
__global__ __launch_bounds__(256) void k5_dw_gelu(const float* __restrict__ dww)
{
    extern __shared__ __nv_bfloat16 s5b[];   // [10][128][32] bf16
    int tid = threadIdx.x;
    int blk = blockIdx.x;
    int ct = blk & 7, ht = (blk >> 3) & 15, b = blk >> 7;
    int c0 = ct * 32, h0 = ht * 8;
    #pragma unroll
    for (int r = 0; r < 10; ++r) {
        int h = h0 - 1 + r;
        uint4* dst = (uint4*)(s5b + r*4096);
        if ((unsigned)h < 128u) {
            const uint4* src = (const uint4*)(g_f + ((size_t)b*NN + (size_t)h*WW)*HID + c0);
            for (int i = tid; i < 512; i += 256) {
                int px = i >> 2, q = i & 3;
                dst[i] = src[px*32 + q];
            }
        } else {
            uint4 z = make_uint4(0u,0u,0u,0u);
            for (int i = tid; i < 512; i += 256) dst[i] = z;
        }
    }
    __syncthreads();

    int cp = tid & 15, wi = tid >> 4;
    float2 wt[9];
    #pragma unroll
    for (int t = 0; t < 9; ++t)
        wt[t] = *(const float2*)&dww[t*HID + c0 + 2*cp];

    const __nv_bfloat162* s5p = (const __nv_bfloat162*)s5b;

    #pragma unroll
    for (int ro = 0; ro < 8; ++ro) {
        const __nv_bfloat162* r0p = s5p + ro*2048 + cp;
        const __nv_bfloat162* r1p = r0p + 2048;
        const __nv_bfloat162* r2p = r1p + 2048;
        int w = wi * 8;
        float2 L0, L1, L2, C0, C1, C2;
        if (w == 0) {
            L0 = L1 = L2 = make_float2(0.f, 0.f);
        } else {
            L0 = __bfloat1622float2(r0p[(w-1)*16]);
            L1 = __bfloat1622float2(r1p[(w-1)*16]);
            L2 = __bfloat1622float2(r2p[(w-1)*16]);
        }
        C0 = __bfloat1622float2(r0p[w*16]);
        C1 = __bfloat1622float2(r1p[w*16]);
        C2 = __bfloat1622float2(r2p[w*16]);
        #pragma unroll
        for (int k = 0; k < 8; ++k) {
            float2 N0, N1, N2;
            if (w + 1 < 128) {
                N0 = __bfloat1622float2(r0p[(w+1)*16]);
                N1 = __bfloat1622float2(r1p[(w+1)*16]);
                N2 = __bfloat1622float2(r2p[(w+1)*16]);
            } else {
                N0 = N1 = N2 = make_float2(0.f, 0.f);
            }
            float2 acc = make_float2(0.f, 0.f);
            acc = ffma2(L0, wt[0], acc); acc = ffma2(C0, wt[1], acc); acc = ffma2(N0, wt[2], acc);
            acc = ffma2(L1, wt[3], acc); acc = ffma2(C1, wt[4], acc); acc = ffma2(N1, wt[5], acc);
            acc = ffma2(L2, wt[6], acc); acc = ffma2(C2, wt[7], acc); acc = ffma2(N2, wt[8], acc);
            float2 o;
            o.x = acc.x * normcdff(acc.x);
            o.y = acc.y * normcdff(acc.y);
            *(__nv_bfloat162*)&g_g[((size_t)b*NN + (size_t)(h0+ro)*WW + w)*HID + c0 + 2*cp] =
                __float22bfloat162_rn(o);
            L0 = C0; L1 = C1; L2 = C2;
            C0 = N0; C1 = N1; C2 = N2;
            ++w;
        }
    }
}

// =====================================================================
// K6: fc2 (256->64) + residual via bf16 m16n8k16 mma. grid 1024, block 256.
// smem: WF 8192 words (32 KB) + As [128][264] bf16 (67.5 KB) = 100352 B.
// Single A stage (no kblk loop).
// =====================================================================
__global__ __launch_bounds__(256) void k6_fc2(
    const float* __restrict__ w2, const float* __restrict__ b2,
    float* __restrict__ out)
{
    extern __shared__ char sm6raw[];
    unsigned* WFw = (unsigned*)sm6raw;                    // [8 nt][16 kc][32 ln][2 j]
    __nv_bfloat16* As = (__nv_bfloat16*)(sm6raw + 32768); // [128][264]
    int tid = threadIdx.x, warp = tid >> 5, lane = tid & 31;
    int gid = lane >> 2, tig = lane & 3;
    int rowbase = blockIdx.x * 128;

    for (int idx = tid; idx < 8192; idx += 256) {
        int j = idx & 1, ln = (idx >> 1) & 31, kc = (idx >> 6) & 15, nt = idx >> 10;
        int g_ = ln >> 2, t_ = ln & 3;
        int k0 = kc*16 + 2*t_ + j*8;
        int col = nt*8 + g_;
        __nv_bfloat162 p = __float22bfloat162_rn(
            make_float2(w2[k0*64 + col], w2[(k0+1)*64 + col]));
        WFw[idx] = *(unsigned*)&p;
    }
    {   // stage A: 128 rows x 256 bf16, row stride 264 bf16 = 33 uint4
        uint4* As4 = (uint4*)As;
        for (int i = tid; i < 4096; i += 256) {
            int row = i >> 5, q = i & 31;
            As4[row*33 + q] = *(const uint4*)&g_g[(size_t)(rowbase+row)*HID + q*8];
        }
    }
    __syncthreads();

    const unsigned* Asw = (const unsigned*)As;   // word stride 132 per row
    const uint2* WFu2 = (const uint2*)WFw;
    float acc[8][4];
    #pragma unroll
    for (int nt = 0; nt < 8; ++nt)
        #pragma unroll
        for (int r = 0; r < 4; ++r) acc[nt][r] = 0.f;

    #pragma unroll 4
    for (int kc = 0; kc < 16; ++kc) {
        unsigned a[4];
        int base = (warp*16 + gid)*132 + kc*8;
        a[0] = Asw[base + tig];
        a[1] = Asw[base + 8*132 + tig];
        a[2] = Asw[base + tig + 4];
        a[3] = Asw[base + 8*132 + tig + 4];
        #pragma unroll
        for (int nt = 0; nt < 8; ++nt) {
            uint2 bv = WFu2[(nt*16 + kc)*32 + lane];
            mma_bf16(acc[nt], a, (const unsigned*)&bv);
        }
    }

    #pragma unroll
    for (int nt = 0; nt < 8; ++nt) {
        int col = nt*8 + tig*2;
        float2 bbv = *(const float2*)&b2[col];
        int row = rowbase + warp*16 + gid;
        float2 r0 = *(const float2*)&g_x2[(size_t)row*CC + col];
        float2 r1 = *(const float2*)&g_x2[(size_t)(row+8)*CC + col];
        float2 o0 = make_float2(r0.x + acc[nt][0] + bbv.x, r0.y + acc[nt][1] + bbv.y);
        float2 o1 = make_float2(r1.x + acc[nt][2] + bbv.x, r1.y + acc[nt][3] + bbv.y);
        *(float2*)&out[(size_t)row*CC + col]     = o0;
        *(float2*)&out[(size_t)(row+8)*CC + col] = o1;
    }
}

// =====================================================================
extern "C" void kernel_launch(void* const* d_in, const int* in_sizes, int n_in,
                              void* d_out, int out_size)
{
    const float* x     = (const float*)d_in[0];
    const float* ln1_g = (const float*)d_in[3];
    const float* ln1_b = (const float*)d_in[4];
    const float* q_w   = (const float*)d_in[5];
    const float* q_b   = (const float*)d_in[6];
    const float* kv_w  = (const float*)d_in[7];
    const float* kv_b  = (const float*)d_in[8];
    const float* pr_w  = (const float*)d_in[9];
    const float* pr_b  = (const float*)d_in[10];
    const float* sr_w  = (const float*)d_in[11];
    const float* sr_b  = (const float*)d_in[12];
    const float* srn_g = (const float*)d_in[13];
    const float* srn_b = (const float*)d_in[14];
    const float* ln2_g = (const float*)d_in[15];
    const float* ln2_b = (const float*)d_in[16];
    const float* fc1_w = (const float*)d_in[17];
    const float* fc1_b = (const float*)d_in[18];
    const float* dw_w  = (const float*)d_in[19];
    const float* fc2_w = (const float*)d_in[20];
    const float* fc2_b = (const float*)d_in[21];
    float* out = (float*)d_out;

    const int K1_SMEM = (4096 + 128*68) * 4;                    // 51200
    const int K2_SMEM = 2*16*68*4;                              // 8704
    const int K3_SMEM = (16384 + 16384 + 64*260 + 64*68) * 4;   // 215040
    const int K4_SMEM = 16384 + 128*72*2;                       // 34816
    const int K5_SMEM = 10*128*32*2;                            // 81920
    const int K6_SMEM = 32768 + 128*264*2;                      // 100352

    cudaFuncSetAttribute(k1_ln_q,   cudaFuncAttributeMaxDynamicSharedMemorySize, K1_SMEM);
    cudaFuncSetAttribute(k3_attn,   cudaFuncAttributeMaxDynamicSharedMemorySize, K3_SMEM);
    cudaFuncSetAttribute(k4_ln_fc1, cudaFuncAttributeMaxDynamicSharedMemorySize, K4_SMEM);
    cudaFuncSetAttribute(k5_dw_gelu,cudaFuncAttributeMaxDynamicSharedMemorySize, K5_SMEM);
    cudaFuncSetAttribute(k6_fc2,    cudaFuncAttributeMaxDynamicSharedMemorySize, K6_SMEM);

    k1_ln_q  <<<1024, 256, K1_SMEM>>>(x, ln1_g, ln1_b, q_w, q_b);
    k2w_pack <<<1024, 256>>>(sr_w);
    k2_sr_kv <<<128, 256, K2_SMEM>>>(sr_b, srn_g, srn_b, kv_w, kv_b, pr_w);
    k3_attn  <<<512, 512, K3_SMEM>>>(x, pr_b);
    k4_ln_fc1<<<2048, 256, K4_SMEM>>>(ln2_g, ln2_b, fc1_w, fc1_b);
    k5_dw_gelu<<<1024, 256, K5_SMEM>>>(dw_w);
    k6_fc2   <<<1024, 256, K6_SMEM>>>(fc2_w, fc2_b, out);
}